// round 5
// baseline (speedup 1.0000x reference)
#include <cuda_runtime.h>

typedef unsigned long long u64;

#define B_   256
#define T_   512
#define NIN  512
#define H_   256
#define G3H  768
#define NC   101
#define GB   64      // GRU CTAs
#define NB   4       // batches per GRU CTA
#define KC   32      // k-pairs (of 128) cached in smem
#define SMEM_GRU (KC * G3H * 8 + 2 * NB * H_ * 4)   // 196608 + 8192 = 204800

// ---- scratch (device globals; allocation-free) ----------------------------
__device__ float g_xg[(size_t)B_ * T_ * G3H];  // [B*T, 3H] input gate proj
__device__ u64   g_Wt[128 * G3H];              // W_hh transposed, f32-pairs as u64
__device__ float g_hT[B_ * H_];                // final hidden state

// ---- packed f32x2 helpers -------------------------------------------------
__device__ __forceinline__ void fma2(u64& d, u64 a, u64 b) {
    asm("fma.rn.f32x2 %0, %1, %2, %0;" : "+l"(d) : "l"(a), "l"(b));
}
__device__ __forceinline__ u64 dup2(float a) {
    u64 u; asm("mov.b64 %0, {%1,%1};" : "=l"(u) : "f"(a)); return u;
}
__device__ __forceinline__ float2 unpk(u64 v) {
    float2 r; asm("mov.b64 {%0,%1}, %2;" : "=f"(r.x), "=f"(r.y) : "l"(v)); return r;
}
__device__ __forceinline__ float hsum(u64 v) { float2 f = unpk(v); return f.x + f.y; }

// ===========================================================================
// Kernel A: xg[m,g] = sum_k x[m,k]*W_ih[g,k] + b_ih[g]
// SGEMM-NT 128x128x8, 256 thr, 8x8 microtile, f32x2, double-buffered smem.
// ===========================================================================
__global__ __launch_bounds__(256)
void xg_gemm(const float* __restrict__ x, const float* __restrict__ Wih,
             const float* __restrict__ bih) {
    __shared__ float As[2][8][128];
    __shared__ float Bs[2][8][128];
    const int tid = threadIdx.x;
    const int tx = tid & 15, ty = tid >> 4;
    const int mBase = blockIdx.y * 128;
    const int nBase = blockIdx.x * 128;
    const int lrow = tid >> 1;
    const int lks  = (tid & 1) * 4;

    const float* aPtr = x   + (size_t)(mBase + lrow) * NIN + lks;
    const float* bPtr = Wih + (size_t)(nBase + lrow) * NIN + lks;

    float4 a4 = *(const float4*)aPtr;
    float4 b4 = *(const float4*)bPtr;
    #pragma unroll
    for (int q = 0; q < 4; q++) {
        As[0][lks + q][lrow] = ((const float*)&a4)[q];
        Bs[0][lks + q][lrow] = ((const float*)&b4)[q];
    }
    __syncthreads();

    u64 c[8][4];
    #pragma unroll
    for (int i = 0; i < 8; i++)
        #pragma unroll
        for (int jj = 0; jj < 4; jj++) c[i][jj] = 0ull;

    const int m0 = ty * 8, n0 = tx * 8;
    for (int kt = 0; kt < 64; kt++) {
        const int buf = kt & 1;
        if (kt < 63) {
            a4 = *(const float4*)(aPtr + (kt + 1) * 8);
            b4 = *(const float4*)(bPtr + (kt + 1) * 8);
        }
        #pragma unroll
        for (int k = 0; k < 8; k++) {
            float4 aA = *(const float4*)&As[buf][k][m0];
            float4 aB = *(const float4*)&As[buf][k][m0 + 4];
            u64 bb[4];
            #pragma unroll
            for (int jj = 0; jj < 4; jj++)
                bb[jj] = *(const u64*)&Bs[buf][k][n0 + 2 * jj];
            float av[8] = { aA.x, aA.y, aA.z, aA.w, aB.x, aB.y, aB.z, aB.w };
            #pragma unroll
            for (int i = 0; i < 8; i++) {
                u64 ad = dup2(av[i]);
                #pragma unroll
                for (int jj = 0; jj < 4; jj++) fma2(c[i][jj], ad, bb[jj]);
            }
        }
        if (kt < 63) {
            const int nb = buf ^ 1;
            #pragma unroll
            for (int q = 0; q < 4; q++) {
                As[nb][lks + q][lrow] = ((const float*)&a4)[q];
                Bs[nb][lks + q][lrow] = ((const float*)&b4)[q];
            }
        }
        __syncthreads();
    }

    float* out = g_xg + (size_t)(mBase + m0) * G3H + nBase + n0;
    #pragma unroll
    for (int i = 0; i < 8; i++) {
        #pragma unroll
        for (int jj = 0; jj < 4; jj++) {
            float2 v = unpk(c[i][jj]);
            int col = nBase + n0 + 2 * jj;
            v.x += bih[col]; v.y += bih[col + 1];
            *(float2*)(out + (size_t)i * G3H + 2 * jj) = v;
        }
    }
}

// ===========================================================================
// Kernel B0: transpose W_hh [768,256] -> g_Wt[k2][row] (u64 f32-pairs)
// ===========================================================================
__global__ void wt_kernel(const float* __restrict__ Whh) {
    int i = blockIdx.x * blockDim.x + threadIdx.x;   // 0 .. 128*768-1
    if (i >= 128 * G3H) return;
    int row = i >> 7;
    int k2  = i & 127;
    float2 v = make_float2(Whh[row * H_ + 2 * k2], Whh[row * H_ + 2 * k2 + 1]);
    g_Wt[(size_t)k2 * G3H + row] = *(u64*)&v;
}

// ===========================================================================
// Kernel B: batch-parallel GRU. 64 CTAs x 4 batches, 256 thr (unit j per thr).
// First KC k-pairs of W from smem; rest streamed from L2, reg-double-buffered.
// One __syncthreads per timestep.
// ===========================================================================
#define LOADW(dst, kb)                                                        \
    _Pragma("unroll")                                                         \
    for (int u = 0; u < 4; u++) {                                             \
        const u64* p = g_Wt + (size_t)((kb) + u) * G3H + j;                   \
        (dst)[3*u]   = __ldg(p);                                              \
        (dst)[3*u+1] = __ldg(p + H_);                                         \
        (dst)[3*u+2] = __ldg(p + 2 * H_);                                     \
    }

#define CONSUME(wv, kb)                                                       \
    _Pragma("unroll")                                                         \
    for (int u = 0; u < 4; u++) {                                             \
        _Pragma("unroll")                                                     \
        for (int b = 0; b < NB; b++) {                                        \
            u64 h2 = *(const u64*)&h[b * H_ + 2 * ((kb) + u)];                \
            fma2(ar[b], (wv)[3*u],   h2);                                     \
            fma2(az[b], (wv)[3*u+1], h2);                                     \
            fma2(an[b], (wv)[3*u+2], h2);                                     \
        }                                                                     \
    }

__global__ __launch_bounds__(256, 1)
void gru_kernel(const float* __restrict__ bhh) {
    extern __shared__ char smraw[];
    u64*   Wc = (u64*)smraw;                    // [KC][G3H]
    float* hB = (float*)(Wc + KC * G3H);        // [2][NB][H_]

    const int j = threadIdx.x;
    for (int i = j; i < KC * G3H; i += 256) Wc[i] = g_Wt[i];
    #pragma unroll
    for (int b = 0; b < NB; b++) hB[b * H_ + j] = 0.f;

    const float bhr = bhh[j];
    const float bhz = bhh[H_ + j];
    const float bhn = bhh[2 * H_ + j];
    const int b0 = blockIdx.x * NB;
    __syncthreads();

    for (int s = 0; s < T_; s++) {
        const float* h = hB + (s & 1) * (NB * H_);
        float* hnw     = hB + ((s + 1) & 1) * (NB * H_);

        float xr[NB], xz[NB], xn[NB];
        #pragma unroll
        for (int b = 0; b < NB; b++) {
            const float* xp = g_xg + ((size_t)(b0 + b) * T_ + s) * G3H + j;
            xr[b] = xp[0]; xz[b] = xp[H_]; xn[b] = xp[2 * H_];
        }

        u64 ar[NB], az[NB], an[NB];
        #pragma unroll
        for (int b = 0; b < NB; b++) { ar[b] = 0ull; az[b] = 0ull; an[b] = 0ull; }

        // cached region: k2 in [0, KC)
        #pragma unroll 4
        for (int k2 = 0; k2 < KC; k2++) {
            u64 wr = Wc[(size_t)k2 * G3H + j];
            u64 wz = Wc[(size_t)k2 * G3H + H_ + j];
            u64 wn = Wc[(size_t)k2 * G3H + 2 * H_ + j];
            #pragma unroll
            for (int b = 0; b < NB; b++) {
                u64 h2 = *(const u64*)&h[b * H_ + 2 * k2];
                fma2(ar[b], wr, h2); fma2(az[b], wz, h2); fma2(an[b], wn, h2);
            }
        }

        // streamed region: k2 in [KC,128), chunks of 4 k2, ping-pong regs
        u64 w0[12], w1[12];
        LOADW(w0, KC);
        #pragma unroll 1
        for (int c4 = 0; c4 < (128 - KC) / 4; c4 += 2) {
            int kb = KC + c4 * 4;
            LOADW(w1, kb + 4);
            CONSUME(w0, kb);
            if (c4 + 2 < (128 - KC) / 4) { LOADW(w0, kb + 8); }
            CONSUME(w1, kb + 4);
        }

        #pragma unroll
        for (int b = 0; b < NB; b++) {
            float hr = hsum(ar[b]) + bhr;
            float hz = hsum(az[b]) + bhz;
            float hn = hsum(an[b]) + bhn;
            float r = 1.f / (1.f + __expf(-(xr[b] + hr)));
            float z = 1.f / (1.f + __expf(-(xz[b] + hz)));
            float n = tanhf(xn[b] + r * hn);
            float hv = (1.f - z) * n + z * h[b * H_ + j];
            hnw[b * H_ + j] = hv;
            if (s == T_ - 1) g_hT[(b0 + b) * H_ + j] = hv;
        }
        __syncthreads();
    }
}

// ===========================================================================
// Kernel C: out[b,c] = hT[b] . fc_w[c] + fc_b[c]
// ===========================================================================
__global__ void fc_kernel(const float* __restrict__ fcw,
                          const float* __restrict__ fcb,
                          float* __restrict__ out) {
    __shared__ float hs[H_];
    const int b = blockIdx.x;
    for (int i = threadIdx.x; i < H_; i += blockDim.x) hs[i] = g_hT[b * H_ + i];
    __syncthreads();
    const int c = threadIdx.x;
    if (c < NC) {
        float acc = fcb[c];
        const float* w = fcw + (size_t)c * H_;
        #pragma unroll 8
        for (int k = 0; k < H_; k++) acc = fmaf(hs[k], w[k], acc);
        out[(size_t)b * NC + c] = acc;
    }
}

// ===========================================================================
extern "C" void kernel_launch(void* const* d_in, const int* in_sizes, int n_in,
                              void* d_out, int out_size) {
    const float* x   = (const float*)d_in[0];
    const float* Wih = (const float*)d_in[1];
    const float* Whh = (const float*)d_in[2];
    const float* bih = (const float*)d_in[3];
    const float* bhh = (const float*)d_in[4];
    const float* fcw = (const float*)d_in[5];
    const float* fcb = (const float*)d_in[6];
    float* out = (float*)d_out;

    cudaFuncSetAttribute(gru_kernel,
                         cudaFuncAttributeMaxDynamicSharedMemorySize, SMEM_GRU);

    wt_kernel<<<(128 * G3H + 255) / 256, 256>>>(Whh);
    dim3 g1(G3H / 128, (B_ * T_) / 128);
    xg_gemm<<<g1, 256>>>(x, Wih, bih);
    gru_kernel<<<GB, 256, SMEM_GRU>>>(bhh);
    fc_kernel<<<B_, 128>>>(fcw, fcb, out);
}

// round 7
// speedup vs baseline: 2.3921x; 2.3921x over previous
#include <cuda_runtime.h>
#include <cuda_fp16.h>

typedef unsigned long long u64;
typedef unsigned int u32;

#define B_   256
#define T_   512
#define NIN  512
#define H_   256
#define G3H  768
#define NC   101
#define GB   64      // GRU CTAs
#define NB   4       // batches per GRU CTA
#define NG2  128     // k2 pair-groups... (k2 = 0..127; groups of 2 k2 = 64 groups)
#define KCG  32      // 2-k2 groups cached in smem (k2 0..63)
#define SMEM_GRU (KCG * 1536 * 4 + 2 * NB * H_ * 4)   // 196608 + 8192 = 204800

// ---- scratch (device globals; allocation-free) ----------------------------
__device__ float g_xg[(size_t)B_ * T_ * G3H];          // input gate proj, fp32
__device__ __half g_xh[(size_t)B_ * T_ * NIN];         // x in fp16
__device__ __half g_wh[G3H * NIN];                     // W_ih in fp16
__device__ __align__(16) u32 g_Wp[64 * 1536];          // W_hh packed fp16: [g2][gate][j][k2lo|k2hi]
__device__ float g_hT[B_ * H_];                        // final hidden

// ---- packed f32x2 helpers -------------------------------------------------
__device__ __forceinline__ void fma2(u64& d, u64 a, u64 b) {
    asm("fma.rn.f32x2 %0, %1, %2, %0;" : "+l"(d) : "l"(a), "l"(b));
}
__device__ __forceinline__ u64 pk(float2 v) {
    u64 u; asm("mov.b64 %0,{%1,%2};" : "=l"(u) : "f"(v.x), "f"(v.y)); return u;
}
__device__ __forceinline__ float2 unpk(u64 v) {
    float2 r; asm("mov.b64 {%0,%1}, %2;" : "=f"(r.x), "=f"(r.y) : "l"(v)); return r;
}
__device__ __forceinline__ float hsum(u64 v) { float2 f = unpk(v); return f.x + f.y; }

// ---- fp32 -> fp16 conversion (grid-stride over float2) --------------------
__global__ void cvt2h(const float* __restrict__ in, __half2* __restrict__ out, int n2) {
    for (int i = blockIdx.x * blockDim.x + threadIdx.x; i < n2; i += gridDim.x * blockDim.x) {
        float2 v = ((const float2*)in)[i];
        out[i] = __floats2half2_rn(v.x, v.y);
    }
}

// ---- pack W_hh to fp16 [g2][gate][j][2] -----------------------------------
__global__ void pack_whh(const float* __restrict__ Whh) {
    int i = blockIdx.x * blockDim.x + threadIdx.x;    // 0 .. 128*768
    if (i >= 128 * G3H) return;
    int row = i % G3H;            // g*256 + j
    int k2  = i / G3H;            // 0..127
    __half2 v = __floats2half2_rn(Whh[(size_t)row * H_ + 2 * k2],
                                  Whh[(size_t)row * H_ + 2 * k2 + 1]);
    int g = row >> 8, j = row & 255;
    g_Wp[(k2 >> 1) * 1536 + g * 512 + j * 2 + (k2 & 1)] = *(u32*)&v;
}

// ===========================================================================
// Kernel A: fp16 HMMA GEMM: xg[m, n] = sum_k xh[m,k] * wh[n,k] + bih[n]
// CTA tile 128x64, K-tile 32, 8 warps (4m x 2n), warp tile 32x32.
// Swizzled smem (stride 32 halfs, chunk c8 ^= (row>>1)&3), ldmatrix + mma.
// ===========================================================================
__device__ __forceinline__ void lds4(u32& r0, u32& r1, u32& r2, u32& r3, u32 addr) {
    asm volatile("ldmatrix.sync.aligned.m8n8.x4.shared.b16 {%0,%1,%2,%3}, [%4];"
                 : "=r"(r0), "=r"(r1), "=r"(r2), "=r"(r3) : "r"(addr));
}
__device__ __forceinline__ void mma16816(float* c, const u32* a, const u32* b) {
    asm volatile("mma.sync.aligned.m16n8k16.row.col.f32.f16.f16.f32 "
                 "{%0,%1,%2,%3}, {%4,%5,%6,%7}, {%8,%9}, {%0,%1,%2,%3};"
                 : "+f"(c[0]), "+f"(c[1]), "+f"(c[2]), "+f"(c[3])
                 : "r"(a[0]), "r"(a[1]), "r"(a[2]), "r"(a[3]), "r"(b[0]), "r"(b[1]));
}

__global__ __launch_bounds__(256)
void hgemm(const __half* __restrict__ Ah, const __half* __restrict__ Wh,
           const float* __restrict__ bih) {
    __shared__ __half As[2][128 * 32];   // 8KB per stage
    __shared__ __half Bs[2][64 * 32];    // 4KB per stage
    const int tid = threadIdx.x;
    const int lane = tid & 31, warp = tid >> 5;
    const int wm = warp & 3, wn = warp >> 2;
    const size_t mBase = (size_t)blockIdx.y * 128;
    const int nBase = blockIdx.x * 64;

    // loader mapping: thread t -> row lr = t>>2, chunk lc = t&3 (16B chunks)
    const int lr = tid >> 2, lc = tid & 3;
    const uint4* aG0 = (const uint4*)(Ah + (mBase + lr) * NIN) + lc;
    const uint4* aG1 = aG0 + (64 * NIN) / 8;
    const uint4* bG  = (const uint4*)(Wh + (size_t)(nBase + lr) * NIN) + lc;
    const int stA = lr * 64 + ((lc ^ ((lr >> 1) & 3)) * 16);   // byte offset in stage
    const int stB = stA;                                        // same formula (lr<64)

    const u32 aSm = (u32)__cvta_generic_to_shared(&As[0][0]);
    const u32 bSm = (u32)__cvta_generic_to_shared(&Bs[0][0]);

    // ldmatrix lane offsets (bytes within stage)
    const int rowA = wm * 32 + ((lane >> 3) & 1) * 8 + (lane & 7);
    const int loffA = rowA * 64 + (((lane >> 4) ^ ((rowA >> 1) & 3)) * 16);
    const int rowB = wn * 32 + (lane >> 4) * 8 + (lane & 7);
    const int loffB = rowB * 64 + ((((lane >> 3) & 1) ^ ((rowB >> 1) & 3)) * 16);

    float c[2][4][4];
    #pragma unroll
    for (int mi = 0; mi < 2; mi++)
        #pragma unroll
        for (int ni = 0; ni < 4; ni++)
            #pragma unroll
            for (int q = 0; q < 4; q++) c[mi][ni][q] = 0.f;

    // prologue: tile 0
    uint4 ra0 = __ldg(aG0), ra1 = __ldg(aG1), rb0 = __ldg(bG);
    *(uint4*)((char*)As + stA)        = ra0;
    *(uint4*)((char*)As + stA + 4096) = ra1;
    *(uint4*)((char*)Bs + stB)        = rb0;
    __syncthreads();

    for (int kt = 0; kt < 16; kt++) {
        const int stg = kt & 1;
        if (kt < 15) {
            ra0 = __ldg(aG0 + (kt + 1) * 4);
            ra1 = __ldg(aG1 + (kt + 1) * 4);
            rb0 = __ldg(bG  + (kt + 1) * 4);
        }
        const u32 aB = aSm + stg * 8192;
        const u32 bB = bSm + stg * 4096;
        #pragma unroll
        for (int t = 0; t < 2; t++) {
            u32 aF[2][4], bF4[2][4];
            lds4(aF[0][0], aF[0][1], aF[0][2], aF[0][3], aB + (loffA ^ (t << 5)));
            lds4(aF[1][0], aF[1][1], aF[1][2], aF[1][3], aB + ((loffA + 1024) ^ (t << 5)));
            lds4(bF4[0][0], bF4[0][1], bF4[0][2], bF4[0][3], bB + (loffB ^ (t << 5)));
            lds4(bF4[1][0], bF4[1][1], bF4[1][2], bF4[1][3], bB + ((loffB + 1024) ^ (t << 5)));
            // bF4[h][{0,1}] = n8 tile 2h+0 frags, bF4[h][{2,3}] = n8 tile 2h+1
            #pragma unroll
            for (int mi = 0; mi < 2; mi++) {
                mma16816(c[mi][0], aF[mi], &bF4[0][0]);
                mma16816(c[mi][1], aF[mi], &bF4[0][2]);
                mma16816(c[mi][2], aF[mi], &bF4[1][0]);
                mma16816(c[mi][3], aF[mi], &bF4[1][2]);
            }
        }
        if (kt < 15) {
            __syncthreads();
            const int ns = (kt + 1) & 1;
            *(uint4*)((char*)As + ns * 8192 + stA)        = ra0;
            *(uint4*)((char*)As + ns * 8192 + stA + 4096) = ra1;
            *(uint4*)((char*)Bs + ns * 4096 + stB)        = rb0;
            __syncthreads();
        }
    }

    // epilogue: lane -> rows (lane>>2, +8), cols (lane&3)*2 (+1)
    const int er = lane >> 2, ec = (lane & 3) * 2;
    #pragma unroll
    for (int mi = 0; mi < 2; mi++) {
        const size_t m0 = mBase + wm * 32 + mi * 16 + er;
        #pragma unroll
        for (int ni = 0; ni < 4; ni++) {
            const int col = nBase + wn * 32 + ni * 8 + ec;
            const float2 bv = *(const float2*)&bih[col];
            float2 o0 = make_float2(c[mi][ni][0] + bv.x, c[mi][ni][1] + bv.y);
            float2 o1 = make_float2(c[mi][ni][2] + bv.x, c[mi][ni][3] + bv.y);
            *(float2*)(g_xg + m0 * G3H + col)       = o0;
            *(float2*)(g_xg + (m0 + 8) * G3H + col) = o1;
        }
    }
}

// ===========================================================================
// Kernel B: GRU recurrence. 64 CTAs x 4 batches, thread j owns hidden unit j.
// fp16 weights: first 32 2-k2 groups from smem, rest streamed from L2 with a
// 4-slot distance-2 register ring. fp32 h and accumulation (f32x2).
// ===========================================================================
__device__ __forceinline__ void consume(uint2 wr, uint2 wz, uint2 wn_,
                                        const float* hq,
                                        u64* ar, u64* az, u64* an) {
    u64 wr0 = pk(__half22float2(*(__half2*)&wr.x));
    u64 wr1 = pk(__half22float2(*(__half2*)&wr.y));
    u64 wz0 = pk(__half22float2(*(__half2*)&wz.x));
    u64 wz1 = pk(__half22float2(*(__half2*)&wz.y));
    u64 wn0 = pk(__half22float2(*(__half2*)&wn_.x));
    u64 wn1 = pk(__half22float2(*(__half2*)&wn_.y));
    #pragma unroll
    for (int b = 0; b < NB; b++) {
        ulonglong2 hv = *(const ulonglong2*)(hq + b * H_);   // LDS.128 broadcast
        fma2(ar[b], wr0, hv.x); fma2(ar[b], wr1, hv.y);
        fma2(az[b], wz0, hv.x); fma2(az[b], wz1, hv.y);
        fma2(an[b], wn0, hv.x); fma2(an[b], wn1, hv.y);
    }
}

__global__ __launch_bounds__(256, 1)
void gru_kernel(const float* __restrict__ bhh) {
    extern __shared__ char smraw[];
    u32*   Wc = (u32*)smraw;                      // [KCG][1536]
    float* hB = (float*)(Wc + KCG * 1536);        // [2][NB][H_]

    const int j = threadIdx.x;
    {   // cache groups 0..31 (k2 0..63)
        const u64* src = (const u64*)g_Wp;
        u64* dst = (u64*)Wc;
        for (int i = j; i < KCG * 768; i += 256) dst[i] = src[i];
    }
    #pragma unroll
    for (int b = 0; b < NB; b++) hB[b * H_ + j] = 0.f;

    const float bhr = bhh[j];
    const float bhz = bhh[H_ + j];
    const float bhn = bhh[2 * H_ + j];
    const int b0 = blockIdx.x * NB;
    const uint2* gp = (const uint2*)g_Wp;   // uint2 index: g*768 + j (+256/gate)
    __syncthreads();

    for (int s = 0; s < T_; s++) {
        const float* h = hB + (s & 1) * (NB * H_);
        float* hnw     = hB + ((s + 1) & 1) * (NB * H_);

        float xr[NB], xz[NB], xn[NB];
        #pragma unroll
        for (int b = 0; b < NB; b++) {
            const float* xp = g_xg + ((size_t)(b0 + b) * T_ + s) * G3H + j;
            xr[b] = xp[0]; xz[b] = xp[H_]; xn[b] = xp[2 * H_];
        }

        u64 ar[NB], az[NB], an[NB];
        #pragma unroll
        for (int b = 0; b < NB; b++) { ar[b] = 0ull; az[b] = 0ull; an[b] = 0ull; }

        // ---- cached groups 0..31 (smem) ----
        #pragma unroll 4
        for (int g2 = 0; g2 < KCG; g2++) {
            const u32* wp = Wc + g2 * 1536 + 2 * j;
            uint2 wr = *(const uint2*)wp;
            uint2 wz = *(const uint2*)(wp + 512);
            uint2 wq = *(const uint2*)(wp + 1024);
            consume(wr, wz, wq, h + g2 * 4, ar, az, an);
        }

        // ---- streamed groups 32..63 (L2), 4-slot ring, distance 2 ----
        uint2 wb[4][3];
        #pragma unroll
        for (int p = 0; p < 2; p++) {
            const uint2* q = gp + (size_t)(KCG + p) * 768 + j;
            wb[p][0] = __ldg(q); wb[p][1] = __ldg(q + 256); wb[p][2] = __ldg(q + 512);
        }
        #pragma unroll 4
        for (int i = 0; i < 32; i++) {
            if (i < 30) {
                const uint2* q = gp + (size_t)(KCG + i + 2) * 768 + j;
                wb[(i + 2) & 3][0] = __ldg(q);
                wb[(i + 2) & 3][1] = __ldg(q + 256);
                wb[(i + 2) & 3][2] = __ldg(q + 512);
            }
            consume(wb[i & 3][0], wb[i & 3][1], wb[i & 3][2],
                    h + (KCG + i) * 4, ar, az, an);
        }

        // ---- gates + update ----
        #pragma unroll
        for (int b = 0; b < NB; b++) {
            float hr = hsum(ar[b]) + bhr;
            float hz = hsum(az[b]) + bhz;
            float hn = hsum(an[b]) + bhn;
            float r = 1.f / (1.f + __expf(-(xr[b] + hr)));
            float z = 1.f / (1.f + __expf(-(xz[b] + hz)));
            float n = tanhf(xn[b] + r * hn);
            float hv = (1.f - z) * n + z * h[b * H_ + j];
            hnw[b * H_ + j] = hv;
            if (s == T_ - 1) g_hT[(b0 + b) * H_ + j] = hv;
        }
        __syncthreads();
    }
}

// ===========================================================================
// Kernel C: out[b,c] = hT[b] . fc_w[c] + fc_b[c]
// ===========================================================================
__global__ void fc_kernel(const float* __restrict__ fcw,
                          const float* __restrict__ fcb,
                          float* __restrict__ out) {
    __shared__ float hs[H_];
    const int b = blockIdx.x;
    for (int i = threadIdx.x; i < H_; i += blockDim.x) hs[i] = g_hT[b * H_ + i];
    __syncthreads();
    const int c = threadIdx.x;
    if (c < NC) {
        float acc = fcb[c];
        const float* w = fcw + (size_t)c * H_;
        #pragma unroll 8
        for (int k = 0; k < H_; k++) acc = fmaf(hs[k], w[k], acc);
        out[(size_t)b * NC + c] = acc;
    }
}

// ===========================================================================
extern "C" void kernel_launch(void* const* d_in, const int* in_sizes, int n_in,
                              void* d_out, int out_size) {
    const float* x   = (const float*)d_in[0];
    const float* Wih = (const float*)d_in[1];
    const float* Whh = (const float*)d_in[2];
    const float* bih = (const float*)d_in[3];
    const float* bhh = (const float*)d_in[4];
    const float* fcw = (const float*)d_in[5];
    const float* fcb = (const float*)d_in[6];
    float* out = (float*)d_out;

    cudaFuncSetAttribute(gru_kernel,
                         cudaFuncAttributeMaxDynamicSharedMemorySize, SMEM_GRU);

    // resolve device-global addresses for conversion outputs
    __half2* xh2; cudaGetSymbolAddress((void**)&xh2, g_xh);
    __half2* wh2; cudaGetSymbolAddress((void**)&wh2, g_wh);

    cvt2h<<<2048, 256>>>(x, xh2, (B_ * T_ * NIN) / 2);
    cvt2h<<<256, 256>>>(Wih, wh2, (G3H * NIN) / 2);
    pack_whh<<<(128 * G3H + 255) / 256, 256>>>(Whh);

    __half* xh; cudaGetSymbolAddress((void**)&xh, g_xh);
    __half* wh; cudaGetSymbolAddress((void**)&wh, g_wh);
    dim3 g1(G3H / 64, (B_ * T_) / 128);
    hgemm<<<g1, 256>>>(xh, wh, bih);

    gru_kernel<<<GB, 256, SMEM_GRU>>>(bhh);
    fc_kernel<<<B_, 128>>>(fcw, fcb, out);
}

// round 9
// speedup vs baseline: 4.5948x; 1.9208x over previous
#include <cuda_runtime.h>
#include <cuda_fp16.h>

typedef unsigned long long u64;
typedef unsigned int u32;

#define B_   256
#define T_   512
#define NIN  512
#define H_   256
#define G3H  768
#define NC   101
#define CL   4        // cluster size (gate-row split)
#define NBG  16       // batches per group (= real MMA M)
#define WROWS 192     // gate rows per CTA (3 gates x 64 j)
#define WBYTES (WROWS * 512)          // 98304 B fp16 W slice
#define ABUF  16384                    // A buffer: hi 8KB + lo 8KB
#define SMEM_GRU (WBYTES + 2 * ABUF)   // 131072

// ---- scratch ---------------------------------------------------------------
__device__ float  g_xg[(size_t)B_ * T_ * G3H];
__device__ __half g_xh[(size_t)B_ * T_ * NIN];
__device__ __half g_wh[G3H * NIN];
__device__ float  g_hT[B_ * H_];

// ---- ptx helpers -----------------------------------------------------------
__device__ __forceinline__ void lds4(u32& r0, u32& r1, u32& r2, u32& r3, u32 a) {
    asm volatile("ldmatrix.sync.aligned.m8n8.x4.shared.b16 {%0,%1,%2,%3}, [%4];"
                 : "=r"(r0), "=r"(r1), "=r"(r2), "=r"(r3) : "r"(a));
}
__device__ __forceinline__ void lds2(u32& r0, u32& r1, u32 a) {
    asm volatile("ldmatrix.sync.aligned.m8n8.x2.shared.b16 {%0,%1}, [%2];"
                 : "=r"(r0), "=r"(r1) : "r"(a));
}
__device__ __forceinline__ void mma16816(float* c, const u32* a, const u32* b) {
    asm volatile("mma.sync.aligned.m16n8k16.row.col.f32.f16.f16.f32 "
                 "{%0,%1,%2,%3}, {%4,%5,%6,%7}, {%8,%9}, {%0,%1,%2,%3};"
                 : "+f"(c[0]), "+f"(c[1]), "+f"(c[2]), "+f"(c[3])
                 : "r"(a[0]), "r"(a[1]), "r"(a[2]), "r"(a[3]), "r"(b[0]), "r"(b[1]));
}
__device__ __forceinline__ u32 mapa_(u32 addr, u32 rank) {
    u32 r; asm("mapa.shared::cluster.u32 %0, %1, %2;" : "=r"(r) : "r"(addr), "r"(rank));
    return r;
}
__device__ __forceinline__ void stclu(u32 addr, u32 v) {
    asm volatile("st.shared::cluster.u32 [%0], %1;" :: "r"(addr), "r"(v) : "memory");
}
__device__ __forceinline__ void cluster_sync() {
    asm volatile("barrier.cluster.arrive.aligned;" ::: "memory");
    asm volatile("barrier.cluster.wait.aligned;" ::: "memory");
}
__device__ __forceinline__ u32 ctarank() {
    u32 r; asm("mov.u32 %0, %%cluster_ctarank;" : "=r"(r)); return r;
}
__device__ __forceinline__ int sw7(int chunk, int row) {
    return (chunk & 24) | ((chunk ^ (row & 7)) & 7);
}

// ---- fp32 -> fp16 convert --------------------------------------------------
__global__ void cvt2h(const float* __restrict__ in, __half2* __restrict__ out, int n2) {
    for (int i = blockIdx.x * blockDim.x + threadIdx.x; i < n2; i += gridDim.x * blockDim.x) {
        float2 v = ((const float2*)in)[i];
        out[i] = __floats2half2_rn(v.x, v.y);
    }
}

// ===========================================================================
// Kernel A: fp16 HMMA GEMM (unchanged from R5): xg = x @ W_ih^T + b_ih
// ===========================================================================
__global__ __launch_bounds__(256)
void hgemm(const __half* __restrict__ Ah, const __half* __restrict__ Wh,
           const float* __restrict__ bih) {
    __shared__ __half As[2][128 * 32];
    __shared__ __half Bs[2][64 * 32];
    const int tid = threadIdx.x;
    const int lane = tid & 31, warp = tid >> 5;
    const int wm = warp & 3, wn = warp >> 2;
    const size_t mBase = (size_t)blockIdx.y * 128;
    const int nBase = blockIdx.x * 64;

    const int lr = tid >> 2, lc = tid & 3;
    const uint4* aG0 = (const uint4*)(Ah + (mBase + lr) * NIN) + lc;
    const uint4* aG1 = aG0 + (64 * NIN) / 8;
    const uint4* bG  = (const uint4*)(Wh + (size_t)(nBase + lr) * NIN) + lc;
    const int stA = lr * 64 + ((lc ^ ((lr >> 1) & 3)) * 16);
    const int stB = stA;

    const u32 aSm = (u32)__cvta_generic_to_shared(&As[0][0]);
    const u32 bSm = (u32)__cvta_generic_to_shared(&Bs[0][0]);

    const int rowA = wm * 32 + ((lane >> 3) & 1) * 8 + (lane & 7);
    const int loffA = rowA * 64 + (((lane >> 4) ^ ((rowA >> 1) & 3)) * 16);
    const int rowB = wn * 32 + (lane >> 4) * 8 + (lane & 7);
    const int loffB = rowB * 64 + ((((lane >> 3) & 1) ^ ((rowB >> 1) & 3)) * 16);

    float c[2][4][4];
    #pragma unroll
    for (int mi = 0; mi < 2; mi++)
        #pragma unroll
        for (int ni = 0; ni < 4; ni++)
            #pragma unroll
            for (int q = 0; q < 4; q++) c[mi][ni][q] = 0.f;

    uint4 ra0 = __ldg(aG0), ra1 = __ldg(aG1), rb0 = __ldg(bG);
    *(uint4*)((char*)As + stA)        = ra0;
    *(uint4*)((char*)As + stA + 4096) = ra1;
    *(uint4*)((char*)Bs + stB)        = rb0;
    __syncthreads();

    for (int kt = 0; kt < 16; kt++) {
        const int stg = kt & 1;
        if (kt < 15) {
            ra0 = __ldg(aG0 + (kt + 1) * 4);
            ra1 = __ldg(aG1 + (kt + 1) * 4);
            rb0 = __ldg(bG  + (kt + 1) * 4);
        }
        const u32 aB = aSm + stg * 8192;
        const u32 bB = bSm + stg * 4096;
        #pragma unroll
        for (int t = 0; t < 2; t++) {
            u32 aF[2][4], bF4[2][4];
            lds4(aF[0][0], aF[0][1], aF[0][2], aF[0][3], aB + (loffA ^ (t << 5)));
            lds4(aF[1][0], aF[1][1], aF[1][2], aF[1][3], aB + ((loffA + 1024) ^ (t << 5)));
            lds4(bF4[0][0], bF4[0][1], bF4[0][2], bF4[0][3], bB + (loffB ^ (t << 5)));
            lds4(bF4[1][0], bF4[1][1], bF4[1][2], bF4[1][3], bB + ((loffB + 1024) ^ (t << 5)));
            #pragma unroll
            for (int mi = 0; mi < 2; mi++) {
                mma16816(c[mi][0], aF[mi], &bF4[0][0]);
                mma16816(c[mi][1], aF[mi], &bF4[0][2]);
                mma16816(c[mi][2], aF[mi], &bF4[1][0]);
                mma16816(c[mi][3], aF[mi], &bF4[1][2]);
            }
        }
        if (kt < 15) {
            __syncthreads();
            const int ns = (kt + 1) & 1;
            *(uint4*)((char*)As + ns * 8192 + stA)        = ra0;
            *(uint4*)((char*)As + ns * 8192 + stA + 4096) = ra1;
            *(uint4*)((char*)Bs + ns * 4096 + stB)        = rb0;
            __syncthreads();
        }
    }

    const int er = lane >> 2, ec = (lane & 3) * 2;
    #pragma unroll
    for (int mi = 0; mi < 2; mi++) {
        const size_t m0 = mBase + wm * 32 + mi * 16 + er;
        #pragma unroll
        for (int ni = 0; ni < 4; ni++) {
            const int col = nBase + wn * 32 + ni * 8 + ec;
            const float2 bv = *(const float2*)&bih[col];
            float2 o0 = make_float2(c[mi][ni][0] + bv.x, c[mi][ni][1] + bv.y);
            float2 o1 = make_float2(c[mi][ni][2] + bv.x, c[mi][ni][3] + bv.y);
            *(float2*)(g_xg + m0 * G3H + col)       = o0;
            *(float2*)(g_xg + (m0 + 8) * G3H + col) = o1;
        }
    }
}

// ===========================================================================
// Kernel B: tensor-core GRU recurrence.
// 16 groups x cluster-of-4. CTA rank q owns j in [q*64, q*64+64), all 3 gates
// (192 W rows, fp16 in smem). M=16 batches. h kept as fp16 hi+lo pair in
// double-buffered smem A operand, replicated to all 4 CTAs via DSMEM.
// Warp w owns j-tile w: smem W rows [w*24 .. w*24+24) = [r(8) z(8) n(8)].
// ===========================================================================
__global__ __launch_bounds__(256, 1) __cluster_dims__(CL, 1, 1)
void gru_mma(const float* __restrict__ Whh, const float* __restrict__ bhh) {
    extern __shared__ char sm[];
    char* WS = sm;                 // [192 rows x 512B] swizzled fp16 W slice
    char* AS = sm + WBYTES;        // [2 bufs][hi 8KB | lo 8KB] h operand

    const int tid = threadIdx.x;
    const int lane = tid & 31, warp = tid >> 5;
    const u32 q = ctarank();
    const int b0 = (blockIdx.x >> 2) * NBG;

    // ---- prologue: load + convert + swizzle W slice ----
    for (int t = tid; t < WROWS * 32; t += 256) {
        int row = t >> 5, ch = t & 31;
        int jt = row / 24, rem = row - jt * 24;
        int g = rem >> 3, rr = rem & 7;
        int grow = g * 256 + (int)q * 64 + jt * 8 + rr;
        const float4* src = (const float4*)(Whh + (size_t)grow * H_ + ch * 8);
        float4 f0 = src[0], f1 = src[1];
        __half2 h0 = __floats2half2_rn(f0.x, f0.y), h1 = __floats2half2_rn(f0.z, f0.w);
        __half2 h2 = __floats2half2_rn(f1.x, f1.y), h3 = __floats2half2_rn(f1.z, f1.w);
        uint4 v = make_uint4(*(u32*)&h0, *(u32*)&h1, *(u32*)&h2, *(u32*)&h3);
        *(uint4*)(WS + row * 512 + sw7(ch, row) * 16) = v;
    }
    for (int t = tid; t < (2 * ABUF) / 16; t += 256)
        ((uint4*)AS)[t] = make_uint4(0, 0, 0, 0);

    // ---- per-thread constants ----
    const int jl = (lane & 3) * 2;
    const int jg = (int)q * 64 + warp * 8 + jl;      // global hidden index j0
    const int m_ = lane >> 2;                        // batch row (and +8)
    const float2 br = *(const float2*)&bhh[jg];
    const float2 bz = *(const float2*)&bhh[256 + jg];
    const float2 bq = *(const float2*)&bhh[512 + jg];

    const float* xg0 = g_xg + (size_t)(b0 + m_) * T_ * G3H + jg;
    const float* xg1 = g_xg + (size_t)(b0 + m_ + 8) * T_ * G3H + jg;

    const u32 wsS = (u32)__cvta_generic_to_shared(WS);
    const u32 asS = (u32)__cvta_generic_to_shared(AS);

    const int arow = ((lane >> 3) & 1) * 8 + (lane & 7);       // A frag rows
    const int achl = (lane >> 4) & 1;
    const int brow = warp * 24 + ((lane >> 4) & 1) * 8 + (lane & 7);  // r,z rows
    const int bchl = (lane >> 3) & 1;
    const int nrow = warp * 24 + 16 + (lane & 7);              // n rows

    // writer byte offsets into an A buffer (hi plane)
    const int chw = (int)q * 8 + warp;                         // k-chunk of j0
    const u32 woff0 = m_ * 512 + sw7(chw, m_) * 16 + (lane & 3) * 4;
    const u32 woff1 = woff0 + 8 * 512;                         // (m+8)&7 == m&7

    u32 asR[CL];
    #pragma unroll
    for (int r = 0; r < CL; r++) asR[r] = mapa_(asS, (u32)r);

    float hOld[4] = {0.f, 0.f, 0.f, 0.f};
    cluster_sync();   // W + zeroed A visible cluster-wide

    for (int s = 0; s < T_; s++) {
        // prefetch this step's input-side gates
        const float* p0 = xg0 + (size_t)s * G3H;
        const float* p1 = xg1 + (size_t)s * G3H;
        const float2 xr0 = *(const float2*)p0;
        const float2 xz0 = *(const float2*)(p0 + 256);
        const float2 xn0 = *(const float2*)(p0 + 512);
        const float2 xr1 = *(const float2*)p1;
        const float2 xz1 = *(const float2*)(p1 + 256);
        const float2 xn1 = *(const float2*)(p1 + 512);

        const u32 abase = asS + (u32)(s & 1) * ABUF;
        float cr[4] = {0, 0, 0, 0}, cz[4] = {0, 0, 0, 0}, cn[4] = {0, 0, 0, 0};

        #pragma unroll 8
        for (int kc = 0; kc < 16; kc++) {
            const int cA = kc * 2 + achl;
            const u32 aaddr = abase + arow * 512 + sw7(cA, arow) * 16;
            u32 ah[4], al[4], bz4[4], bn2[2];
            lds4(ah[0], ah[1], ah[2], ah[3], aaddr);
            lds4(al[0], al[1], al[2], al[3], aaddr + 8192);
            const int cB = kc * 2 + bchl;
            lds4(bz4[0], bz4[1], bz4[2], bz4[3],
                 wsS + brow * 512 + sw7(cB, brow) * 16);
            lds2(bn2[0], bn2[1], wsS + nrow * 512 + sw7(cB, nrow) * 16);
            mma16816(cr, ah, &bz4[0]);
            mma16816(cz, ah, &bz4[2]);
            mma16816(cn, ah, bn2);
            mma16816(cr, al, &bz4[0]);
            mma16816(cz, al, &bz4[2]);
            mma16816(cn, al, bn2);
        }

        // ---- gates: 4 (m,j) values, all register-local ----
        float hv[4];
        {
            const float xr[4] = {xr0.x, xr0.y, xr1.x, xr1.y};
            const float xz[4] = {xz0.x, xz0.y, xz1.x, xz1.y};
            const float xn[4] = {xn0.x, xn0.y, xn1.x, xn1.y};
            const float brv[4] = {br.x, br.y, br.x, br.y};
            const float bzv[4] = {bz.x, bz.y, bz.x, bz.y};
            const float bnv[4] = {bq.x, bq.y, bq.x, bq.y};
            #pragma unroll
            for (int i = 0; i < 4; i++) {
                float rr = 1.f / (1.f + __expf(-(xr[i] + cr[i] + brv[i])));
                float zz = 1.f / (1.f + __expf(-(xz[i] + cz[i] + bzv[i])));
                float nn = tanhf(xn[i] + rr * (cn[i] + bnv[i]));
                hv[i] = (1.f - zz) * nn + zz * hOld[i];
                hOld[i] = hv[i];
            }
        }

        // ---- pack hi/lo and replicate to all 4 CTAs' next A buffer ----
        __half2 hi0 = __floats2half2_rn(hv[0], hv[1]);
        __half2 hi1 = __floats2half2_rn(hv[2], hv[3]);
        float2 f0 = __half22float2(hi0), f1 = __half22float2(hi1);
        __half2 lo0 = __floats2half2_rn(hv[0] - f0.x, hv[1] - f0.y);
        __half2 lo1 = __floats2half2_rn(hv[2] - f1.x, hv[3] - f1.y);
        const u32 nbuf = (u32)((s + 1) & 1) * ABUF;
        #pragma unroll
        for (int r = 0; r < CL; r++) {
            const u32 base = asR[r] + nbuf;
            stclu(base + woff0,        *(u32*)&hi0);
            stclu(base + woff0 + 8192, *(u32*)&lo0);
            stclu(base + woff1,        *(u32*)&hi1);
            stclu(base + woff1 + 8192, *(u32*)&lo1);
        }

        if (s == T_ - 1) {
            *(float2*)(g_hT + (size_t)(b0 + m_) * H_ + jg)     = make_float2(hv[0], hv[1]);
            *(float2*)(g_hT + (size_t)(b0 + m_ + 8) * H_ + jg) = make_float2(hv[2], hv[3]);
        }
        cluster_sync();
    }
}

// ===========================================================================
// Kernel C: out[b,c] = hT[b] . fc_w[c] + fc_b[c]
// ===========================================================================
__global__ void fc_kernel(const float* __restrict__ fcw,
                          const float* __restrict__ fcb,
                          float* __restrict__ out) {
    __shared__ float hs[H_];
    const int b = blockIdx.x;
    for (int i = threadIdx.x; i < H_; i += blockDim.x) hs[i] = g_hT[b * H_ + i];
    __syncthreads();
    const int c = threadIdx.x;
    if (c < NC) {
        float acc = fcb[c];
        const float* w = fcw + (size_t)c * H_;
        #pragma unroll 8
        for (int k = 0; k < H_; k++) acc = fmaf(hs[k], w[k], acc);
        out[(size_t)b * NC + c] = acc;
    }
}

// ===========================================================================
extern "C" void kernel_launch(void* const* d_in, const int* in_sizes, int n_in,
                              void* d_out, int out_size) {
    const float* x   = (const float*)d_in[0];
    const float* Wih = (const float*)d_in[1];
    const float* Whh = (const float*)d_in[2];
    const float* bih = (const float*)d_in[3];
    const float* bhh = (const float*)d_in[4];
    const float* fcw = (const float*)d_in[5];
    const float* fcb = (const float*)d_in[6];
    float* out = (float*)d_out;

    cudaFuncSetAttribute(gru_mma,
                         cudaFuncAttributeMaxDynamicSharedMemorySize, SMEM_GRU);

    __half2* xh2; cudaGetSymbolAddress((void**)&xh2, g_xh);
    __half2* wh2; cudaGetSymbolAddress((void**)&wh2, g_wh);

    cvt2h<<<2048, 256>>>(x, xh2, (B_ * T_ * NIN) / 2);
    cvt2h<<<256, 256>>>(Wih, wh2, (G3H * NIN) / 2);

    __half* xh; cudaGetSymbolAddress((void**)&xh, g_xh);
    __half* wh; cudaGetSymbolAddress((void**)&wh, g_wh);
    dim3 g1(G3H / 64, (B_ * T_) / 128);
    hgemm<<<g1, 256>>>(xh, wh, bih);

    gru_mma<<<16 * CL, 256, SMEM_GRU>>>(Whh, bhh);
    fc_kernel<<<B_, 128>>>(fcw, fcb, out);
}

// round 11
// speedup vs baseline: 5.1372x; 1.1180x over previous
#include <cuda_runtime.h>
#include <cuda_fp16.h>

typedef unsigned long long u64;
typedef unsigned int u32;

#define B_   256
#define T_   512
#define NIN  512
#define H_   256
#define G3H  768
#define NC   101
#define CL   4
#define NBG  16
#define WROWS 192
#define WBYTES (WROWS * 512)
#define ABUF  16384
#define SMEM_GRU (WBYTES + 2 * ABUF)   // 131072

// ---- scratch ---------------------------------------------------------------
__device__ float  g_xg[(size_t)B_ * T_ * G3H];
__device__ __half g_xh[(size_t)B_ * T_ * NIN];
__device__ __half g_wh[G3H * NIN];
__device__ float  g_hT[B_ * H_];

// ---- ptx helpers -----------------------------------------------------------
__device__ __forceinline__ void lds4(u32& r0, u32& r1, u32& r2, u32& r3, u32 a) {
    asm volatile("ldmatrix.sync.aligned.m8n8.x4.shared.b16 {%0,%1,%2,%3}, [%4];"
                 : "=r"(r0), "=r"(r1), "=r"(r2), "=r"(r3) : "r"(a));
}
__device__ __forceinline__ void lds2(u32& r0, u32& r1, u32 a) {
    asm volatile("ldmatrix.sync.aligned.m8n8.x2.shared.b16 {%0,%1}, [%2];"
                 : "=r"(r0), "=r"(r1) : "r"(a));
}
__device__ __forceinline__ void mma16816(float* c, const u32* a, const u32* b) {
    asm volatile("mma.sync.aligned.m16n8k16.row.col.f32.f16.f16.f32 "
                 "{%0,%1,%2,%3}, {%4,%5,%6,%7}, {%8,%9}, {%0,%1,%2,%3};"
                 : "+f"(c[0]), "+f"(c[1]), "+f"(c[2]), "+f"(c[3])
                 : "r"(a[0]), "r"(a[1]), "r"(a[2]), "r"(a[3]), "r"(b[0]), "r"(b[1]));
}
__device__ __forceinline__ u32 mapa_(u32 addr, u32 rank) {
    u32 r; asm("mapa.shared::cluster.u32 %0, %1, %2;" : "=r"(r) : "r"(addr), "r"(rank));
    return r;
}
__device__ __forceinline__ void stclu(u32 addr, u32 v) {
    asm volatile("st.shared::cluster.u32 [%0], %1;" :: "r"(addr), "r"(v) : "memory");
}
__device__ __forceinline__ void cluster_arrive() {
    asm volatile("barrier.cluster.arrive.aligned;" ::: "memory");
}
__device__ __forceinline__ void cluster_wait() {
    asm volatile("barrier.cluster.wait.aligned;" ::: "memory");
}
__device__ __forceinline__ u32 ctarank() {
    u32 r; asm("mov.u32 %0, %%cluster_ctarank;" : "=r"(r)); return r;
}
__device__ __forceinline__ int sw7(int chunk, int row) {
    return (chunk & 24) | ((chunk ^ (row & 7)) & 7);
}

// ---- fp32 -> fp16 convert --------------------------------------------------
__global__ void cvt2h(const float* __restrict__ in, __half2* __restrict__ out, int n2) {
    for (int i = blockIdx.x * blockDim.x + threadIdx.x; i < n2; i += gridDim.x * blockDim.x) {
        float2 v = ((const float2*)in)[i];
        out[i] = __floats2half2_rn(v.x, v.y);
    }
}

// ===========================================================================
// Kernel A: fp16 HMMA GEMM: xg = x @ W_ih^T + b_ih  (unchanged)
// ===========================================================================
__global__ __launch_bounds__(256)
void hgemm(const __half* __restrict__ Ah, const __half* __restrict__ Wh,
           const float* __restrict__ bih) {
    __shared__ __half As[2][128 * 32];
    __shared__ __half Bs[2][64 * 32];
    const int tid = threadIdx.x;
    const int lane = tid & 31, warp = tid >> 5;
    const int wm = warp & 3, wn = warp >> 2;
    const size_t mBase = (size_t)blockIdx.y * 128;
    const int nBase = blockIdx.x * 64;

    const int lr = tid >> 2, lc = tid & 3;
    const uint4* aG0 = (const uint4*)(Ah + (mBase + lr) * NIN) + lc;
    const uint4* aG1 = aG0 + (64 * NIN) / 8;
    const uint4* bG  = (const uint4*)(Wh + (size_t)(nBase + lr) * NIN) + lc;
    const int stA = lr * 64 + ((lc ^ ((lr >> 1) & 3)) * 16);
    const int stB = stA;

    const u32 aSm = (u32)__cvta_generic_to_shared(&As[0][0]);
    const u32 bSm = (u32)__cvta_generic_to_shared(&Bs[0][0]);

    const int rowA = wm * 32 + ((lane >> 3) & 1) * 8 + (lane & 7);
    const int loffA = rowA * 64 + (((lane >> 4) ^ ((rowA >> 1) & 3)) * 16);
    const int rowB = wn * 32 + (lane >> 4) * 8 + (lane & 7);
    const int loffB = rowB * 64 + ((((lane >> 3) & 1) ^ ((rowB >> 1) & 3)) * 16);

    float c[2][4][4];
    #pragma unroll
    for (int mi = 0; mi < 2; mi++)
        #pragma unroll
        for (int ni = 0; ni < 4; ni++)
            #pragma unroll
            for (int q = 0; q < 4; q++) c[mi][ni][q] = 0.f;

    uint4 ra0 = __ldg(aG0), ra1 = __ldg(aG1), rb0 = __ldg(bG);
    *(uint4*)((char*)As + stA)        = ra0;
    *(uint4*)((char*)As + stA + 4096) = ra1;
    *(uint4*)((char*)Bs + stB)        = rb0;
    __syncthreads();

    for (int kt = 0; kt < 16; kt++) {
        const int stg = kt & 1;
        if (kt < 15) {
            ra0 = __ldg(aG0 + (kt + 1) * 4);
            ra1 = __ldg(aG1 + (kt + 1) * 4);
            rb0 = __ldg(bG  + (kt + 1) * 4);
        }
        const u32 aB = aSm + stg * 8192;
        const u32 bB = bSm + stg * 4096;
        #pragma unroll
        for (int t = 0; t < 2; t++) {
            u32 aF[2][4], bF4[2][4];
            lds4(aF[0][0], aF[0][1], aF[0][2], aF[0][3], aB + (loffA ^ (t << 5)));
            lds4(aF[1][0], aF[1][1], aF[1][2], aF[1][3], aB + ((loffA + 1024) ^ (t << 5)));
            lds4(bF4[0][0], bF4[0][1], bF4[0][2], bF4[0][3], bB + (loffB ^ (t << 5)));
            lds4(bF4[1][0], bF4[1][1], bF4[1][2], bF4[1][3], bB + ((loffB + 1024) ^ (t << 5)));
            #pragma unroll
            for (int mi = 0; mi < 2; mi++) {
                mma16816(c[mi][0], aF[mi], &bF4[0][0]);
                mma16816(c[mi][1], aF[mi], &bF4[0][2]);
                mma16816(c[mi][2], aF[mi], &bF4[1][0]);
                mma16816(c[mi][3], aF[mi], &bF4[1][2]);
            }
        }
        if (kt < 15) {
            __syncthreads();
            const int ns = (kt + 1) & 1;
            *(uint4*)((char*)As + ns * 8192 + stA)        = ra0;
            *(uint4*)((char*)As + ns * 8192 + stA + 4096) = ra1;
            *(uint4*)((char*)Bs + ns * 4096 + stB)        = rb0;
            __syncthreads();
        }
    }

    const int er = lane >> 2, ec = (lane & 3) * 2;
    #pragma unroll
    for (int mi = 0; mi < 2; mi++) {
        const size_t m0 = mBase + wm * 32 + mi * 16 + er;
        #pragma unroll
        for (int ni = 0; ni < 4; ni++) {
            const int col = nBase + wn * 32 + ni * 8 + ec;
            const float2 bv = *(const float2*)&bih[col];
            float2 o0 = make_float2(c[mi][ni][0] + bv.x, c[mi][ni][1] + bv.y);
            float2 o1 = make_float2(c[mi][ni][2] + bv.x, c[mi][ni][3] + bv.y);
            *(float2*)(g_xg + m0 * G3H + col)       = o0;
            *(float2*)(g_xg + (m0 + 8) * G3H + col) = o1;
        }
    }
}

// ===========================================================================
// Kernel B: tensor-core GRU, W fragments resident in registers.
// 16 groups x cluster-of-4; per step only the A (h) operand moves: 2 ldmatrix
// per kc (hi/lo planes). Split accumulators shorten MMA dep chains to 16.
// Split cluster barrier: arrive after DSMEM stores, xg prefetch, then wait.
// ===========================================================================
__global__ __launch_bounds__(256, 1) __cluster_dims__(CL, 1, 1)
void gru_mma(const float* __restrict__ Whh, const float* __restrict__ bhh) {
    extern __shared__ char sm[];
    char* WS = sm;                 // staging for W slice (dead after prologue)
    char* AS = sm + WBYTES;        // [2 bufs][hi 8KB | lo 8KB] h operand

    const int tid = threadIdx.x;
    const int lane = tid & 31, warp = tid >> 5;
    const u32 q = ctarank();
    const int b0 = (blockIdx.x >> 2) * NBG;

    // ---- prologue: stage + convert + swizzle W slice into smem ----
    for (int t = tid; t < WROWS * 32; t += 256) {
        int row = t >> 5, ch = t & 31;
        int jt = row / 24, rem = row - jt * 24;
        int g = rem >> 3, rr = rem & 7;
        int grow = g * 256 + (int)q * 64 + jt * 8 + rr;
        const float4* src = (const float4*)(Whh + (size_t)grow * H_ + ch * 8);
        float4 f0 = src[0], f1 = src[1];
        __half2 h0 = __floats2half2_rn(f0.x, f0.y), h1 = __floats2half2_rn(f0.z, f0.w);
        __half2 h2 = __floats2half2_rn(f1.x, f1.y), h3 = __floats2half2_rn(f1.z, f1.w);
        uint4 v = make_uint4(*(u32*)&h0, *(u32*)&h1, *(u32*)&h2, *(u32*)&h3);
        *(uint4*)(WS + row * 512 + sw7(ch, row) * 16) = v;
    }
    for (int t = tid; t < (2 * ABUF) / 16; t += 256)
        ((uint4*)AS)[t] = make_uint4(0, 0, 0, 0);
    __syncthreads();

    // ---- hoist all W fragments into registers (constant across steps) ----
    const u32 wsS = (u32)__cvta_generic_to_shared(WS);
    const int brow = warp * 24 + ((lane >> 4) & 1) * 8 + (lane & 7);
    const int bchl = (lane >> 3) & 1;
    const int nrow = warp * 24 + 16 + (lane & 7);
    u32 bR[16][2], bZ[16][2], bN[16][2];
    #pragma unroll
    for (int kc = 0; kc < 16; kc++) {
        const int cB = kc * 2 + bchl;
        u32 t0, t1, t2, t3;
        lds4(t0, t1, t2, t3, wsS + brow * 512 + sw7(cB, brow) * 16);
        bR[kc][0] = t0; bR[kc][1] = t1; bZ[kc][0] = t2; bZ[kc][1] = t3;
        lds2(bN[kc][0], bN[kc][1], wsS + nrow * 512 + sw7(cB, nrow) * 16);
    }

    // ---- per-thread constants ----
    const int jl = (lane & 3) * 2;
    const int jg = (int)q * 64 + warp * 8 + jl;
    const int m_ = lane >> 2;
    const float2 br = *(const float2*)&bhh[jg];
    const float2 bz = *(const float2*)&bhh[256 + jg];
    const float2 bq = *(const float2*)&bhh[512 + jg];

    const float* xg0 = g_xg + (size_t)(b0 + m_) * T_ * G3H + jg;
    const float* xg1 = g_xg + (size_t)(b0 + m_ + 8) * T_ * G3H + jg;

    const u32 asS = (u32)__cvta_generic_to_shared(AS);
    const int arow = ((lane >> 3) & 1) * 8 + (lane & 7);
    const int achl = (lane >> 4) & 1;

    const int chw = (int)q * 8 + warp;
    const u32 woff0 = m_ * 512 + sw7(chw, m_) * 16 + (lane & 3) * 4;
    const u32 woff1 = woff0 + 8 * 512;

    u32 asR[CL];
    #pragma unroll
    for (int r = 0; r < CL; r++) asR[r] = mapa_(asS, (u32)r);

    float hOld[4] = {0.f, 0.f, 0.f, 0.f};

    // step-0 xg prefetch
    float2 xr0 = *(const float2*)xg0;
    float2 xz0 = *(const float2*)(xg0 + 256);
    float2 xn0 = *(const float2*)(xg0 + 512);
    float2 xr1 = *(const float2*)xg1;
    float2 xz1 = *(const float2*)(xg1 + 256);
    float2 xn1 = *(const float2*)(xg1 + 512);

    cluster_arrive(); cluster_wait();   // W + zeroed A visible cluster-wide

    for (int s = 0; s < T_; s++) {
        const u32 abase = asS + (u32)(s & 1) * ABUF;
        float crh[4] = {0,0,0,0}, czh[4] = {0,0,0,0}, cnh[4] = {0,0,0,0};
        float crl[4] = {0,0,0,0}, czl[4] = {0,0,0,0}, cnl[4] = {0,0,0,0};

        #pragma unroll
        for (int kc = 0; kc < 16; kc++) {
            const int cA = kc * 2 + achl;
            const u32 aaddr = abase + arow * 512 + sw7(cA, arow) * 16;
            u32 ah[4], al[4];
            lds4(ah[0], ah[1], ah[2], ah[3], aaddr);
            lds4(al[0], al[1], al[2], al[3], aaddr + 8192);
            mma16816(crh, ah, bR[kc]);
            mma16816(czh, ah, bZ[kc]);
            mma16816(cnh, ah, bN[kc]);
            mma16816(crl, al, bR[kc]);
            mma16816(czl, al, bZ[kc]);
            mma16816(cnl, al, bN[kc]);
        }

        // ---- gates ----
        float hv[4];
        {
            const float xr[4] = {xr0.x, xr0.y, xr1.x, xr1.y};
            const float xz[4] = {xz0.x, xz0.y, xz1.x, xz1.y};
            const float xn[4] = {xn0.x, xn0.y, xn1.x, xn1.y};
            const float brv[4] = {br.x, br.y, br.x, br.y};
            const float bzv[4] = {bz.x, bz.y, bz.x, bz.y};
            const float bnv[4] = {bq.x, bq.y, bq.x, bq.y};
            #pragma unroll
            for (int i = 0; i < 4; i++) {
                float rr = 1.f / (1.f + __expf(-(xr[i] + crh[i] + crl[i] + brv[i])));
                float zz = 1.f / (1.f + __expf(-(xz[i] + czh[i] + czl[i] + bzv[i])));
                float nn = tanhf(xn[i] + rr * (cnh[i] + cnl[i] + bnv[i]));
                hv[i] = (1.f - zz) * nn + zz * hOld[i];
                hOld[i] = hv[i];
            }
        }

        // ---- replicate h (hi/lo fp16) to all CTAs' next A buffer ----
        __half2 hi0 = __floats2half2_rn(hv[0], hv[1]);
        __half2 hi1 = __floats2half2_rn(hv[2], hv[3]);
        float2 f0 = __half22float2(hi0), f1 = __half22float2(hi1);
        __half2 lo0 = __floats2half2_rn(hv[0] - f0.x, hv[1] - f0.y);
        __half2 lo1 = __floats2half2_rn(hv[2] - f1.x, hv[3] - f1.y);
        const u32 nbuf = (u32)((s + 1) & 1) * ABUF;
        #pragma unroll
        for (int r = 0; r < CL; r++) {
            const u32 base = asR[r] + nbuf;
            stclu(base + woff0,        *(u32*)&hi0);
            stclu(base + woff0 + 8192, *(u32*)&lo0);
            stclu(base + woff1,        *(u32*)&hi1);
            stclu(base + woff1 + 8192, *(u32*)&lo1);
        }
        cluster_arrive();

        // hide next-step xg LDG (and final hT store) under the barrier wait
        if (s < T_ - 1) {
            const float* p0 = xg0 + (size_t)(s + 1) * G3H;
            const float* p1 = xg1 + (size_t)(s + 1) * G3H;
            xr0 = *(const float2*)p0;
            xz0 = *(const float2*)(p0 + 256);
            xn0 = *(const float2*)(p0 + 512);
            xr1 = *(const float2*)p1;
            xz1 = *(const float2*)(p1 + 256);
            xn1 = *(const float2*)(p1 + 512);
        } else {
            *(float2*)(g_hT + (size_t)(b0 + m_) * H_ + jg)     = make_float2(hv[0], hv[1]);
            *(float2*)(g_hT + (size_t)(b0 + m_ + 8) * H_ + jg) = make_float2(hv[2], hv[3]);
        }
        cluster_wait();
    }
}

// ===========================================================================
// Kernel C: out[b,c] = hT[b] . fc_w[c] + fc_b[c], 8 batches/CTA (w reuse)
// ===========================================================================
#define NBF 8
__global__ void fc_kernel(const float* __restrict__ fcw,
                          const float* __restrict__ fcb,
                          float* __restrict__ out) {
    __shared__ float hs[NBF][H_];
    const int b0 = blockIdx.x * NBF;
    for (int i = threadIdx.x; i < NBF * H_; i += blockDim.x)
        hs[i >> 8][i & 255] = g_hT[(size_t)b0 * H_ + i];
    __syncthreads();
    const int c = threadIdx.x;
    if (c < NC) {
        float acc[NBF];
        #pragma unroll
        for (int b = 0; b < NBF; b++) acc[b] = fcb[c];
        const float* w = fcw + (size_t)c * H_;
        #pragma unroll 4
        for (int k = 0; k < H_; k++) {
            float wv = w[k];
            #pragma unroll
            for (int b = 0; b < NBF; b++) acc[b] = fmaf(hs[b][k], wv, acc[b]);
        }
        #pragma unroll
        for (int b = 0; b < NBF; b++) out[(size_t)(b0 + b) * NC + c] = acc[b];
    }
}

// ===========================================================================
extern "C" void kernel_launch(void* const* d_in, const int* in_sizes, int n_in,
                              void* d_out, int out_size) {
    const float* x   = (const float*)d_in[0];
    const float* Wih = (const float*)d_in[1];
    const float* Whh = (const float*)d_in[2];
    const float* bih = (const float*)d_in[3];
    const float* bhh = (const float*)d_in[4];
    const float* fcw = (const float*)d_in[5];
    const float* fcb = (const float*)d_in[6];
    float* out = (float*)d_out;

    cudaFuncSetAttribute(gru_mma,
                         cudaFuncAttributeMaxDynamicSharedMemorySize, SMEM_GRU);

    __half2* xh2; cudaGetSymbolAddress((void**)&xh2, g_xh);
    __half2* wh2; cudaGetSymbolAddress((void**)&wh2, g_wh);

    cvt2h<<<2048, 256>>>(x, xh2, (B_ * T_ * NIN) / 2);
    cvt2h<<<256, 256>>>(Wih, wh2, (G3H * NIN) / 2);

    __half* xh; cudaGetSymbolAddress((void**)&xh, g_xh);
    __half* wh; cudaGetSymbolAddress((void**)&wh, g_wh);
    dim3 g1(G3H / 64, (B_ * T_) / 128);
    hgemm<<<g1, 256>>>(xh, wh, bih);

    gru_mma<<<16 * CL, 256, SMEM_GRU>>>(Whh, bhh);
    fc_kernel<<<B_ / NBF, 128>>>(fcw, fcb, out);
}